// round 2
// baseline (speedup 1.0000x reference)
#include <cuda_runtime.h>
#include <cstdint>

#define THREADS 896     // 28 warps
#define EPT 2           // elements per thread
#define NMODE 256
#define RCORE 8

// Shared memory layout (floats):
//   mid[0]: 16384  (64KB)  double-buffered middle-core slab
//   mid[1]: 16384  (64KB)
//   g0s   : 2048   (8KB)   G0, layout [idx][r]
//   g7s   : 2048   (8KB)   G7 transposed, layout [idx][r]
#define SMEM_BYTES 147456

// Stage one middle core (8 x 256 x 8 floats = 4096 float4 chunks).
// Global float4 index g = r*512 + u   (u = idx*2 + half)
// Shared float4 index s = idx*16 + half*8 + r   (slice contiguous, chunk bankgroup = r)
// Lane mapping: r = lane>>2 (8 groups x 4 lanes -> conflict-free STS),
// 4 consecutive lanes read 64B contiguous global.
__device__ __forceinline__ void stage_mid(float* dst, const float* __restrict__ src, int tid)
{
    const int lane = tid & 31;
    const int wrp  = tid >> 5;          // 0..27
    const int r    = lane >> 2;
    const int m    = lane & 3;
    const char* gbase = (const char*)src;
    unsigned sbase = (unsigned)__cvta_generic_to_shared(dst);
    const int ub = wrp * 4 + m;         // 0..111
#pragma unroll
    for (int t = 0; t < 5; t++) {
        int u = ub + t * 112;
        if (u < 512) {
            long goff = ((long)(r * 512 + u)) << 4;
            unsigned soff = (unsigned)((((u >> 1) << 4) + ((u & 1) << 3) + r) << 4);
            asm volatile("cp.async.cg.shared.global [%0], [%1], 16;\n"
                         :: "r"(sbase + soff), "l"(gbase + goff) : "memory");
        }
    }
    asm volatile("cp.async.commit_group;\n" ::: "memory");
}

__global__ void __launch_bounds__(THREADS, 1)
tt_gather_kernel(const float* __restrict__ G0, const float* __restrict__ G1,
                 const float* __restrict__ G2, const float* __restrict__ G3,
                 const float* __restrict__ G4, const float* __restrict__ G5,
                 const float* __restrict__ G6, const float* __restrict__ G7,
                 const int* __restrict__ states, const int* __restrict__ actions,
                 float* __restrict__ out, int Btot)
{
    extern __shared__ float smem[];
    float* mid0 = smem;
    float* mid1 = smem + 16384;
    float* g0s  = smem + 32768;
    float* g7s  = smem + 34816;

    const int tid = threadIdx.x;
    const int rho = tid & 7;

    // Kick off async staging of G1 into mid0 immediately.
    stage_mid(mid0, G1, tid);

    // Stage G0 (1 x 256 x 8 floats = 512 float4) — already [idx][r] in global.
    if (tid < 512)
        ((float4*)g0s)[tid] = ((const float4*)G0)[tid];

    // Stage G7 transposed: global [r][idx] (8 x 256) -> smem [idx][r].
#pragma unroll
    for (int i = tid; i < 2048; i += THREADS) {
        int idx = i & 255, r = i >> 8;
        g7s[idx * 8 + r] = G7[r * 256 + idx];
    }

    // Per-thread rotated chunk byte offsets (constant for whole kernel).
    int roff[8];
#pragma unroll
    for (int c = 0; c < 8; c++) roff[c] = ((c + rho) & 7) << 4;

    // Load indices for my EPT elements.
    const int base = blockIdx.x * (THREADS * EPT) + tid;
    unsigned actmask = 0;
    int g0off[EPT], g7off[EPT], soff[EPT][6];
#pragma unroll
    for (int i = 0; i < EPT; i++) {
        int e = base + i * THREADS;
        bool act = (e < Btot);
        int ec = act ? e : 0;
        if (act) actmask |= (1u << i);
        const int* sp = states + ec * 7;
        g0off[i] = __ldg(sp);
#pragma unroll
        for (int k = 0; k < 6; k++) soff[i][k] = __ldg(sp + k + 1) << 8;  // idx*256 bytes
        g7off[i] = __ldg(actions + ec);
    }

    asm volatile("cp.async.wait_group 0;\n" ::: "memory");
    __syncthreads();

    // Init rotated vec from G0: w[j] = vec0[(j+rho)&7]
    float w[EPT][8];
#pragma unroll
    for (int i = 0; i < EPT; i++) {
        const char* p0 = (const char*)(g0s) + g0off[i] * 32;
#pragma unroll
        for (int j = 0; j < 8; j++) w[i][j] = *(const float*)(p0 + (roff[j] >> 2));
    }

    const float* nextG[6] = { G1, G2, G3, G4, G5, G6 };  // nextG[k] = core (k+1)

#pragma unroll
    for (int k = 1; k <= 6; k++) {
        const float* cur = (k & 1) ? mid0 : mid1;
        if (k < 6) stage_mid((k & 1) ? mid1 : mid0, nextG[k], tid);

#pragma unroll
        for (int i = 0; i < EPT; i++) {
            const char* p = (const char*)cur + soff[i][k - 1];
            float nv[8];
#pragma unroll
            for (int s = 0; s < 8; s++) nv[s] = 0.f;
#pragma unroll
            for (int c = 0; c < 8; c++) {
                // chunk (r = (c+rho)&7, half): warp's 32 lanes hit all 8 bank-groups 4x
                const float4 glo = *(const float4*)(p + roff[c]);
                const float4 ghi = *(const float4*)(p + 128 + roff[c]);
                const float wc = w[i][c];
                nv[0] = fmaf(wc, glo.x, nv[0]);
                nv[1] = fmaf(wc, glo.y, nv[1]);
                nv[2] = fmaf(wc, glo.z, nv[2]);
                nv[3] = fmaf(wc, glo.w, nv[3]);
                nv[4] = fmaf(wc, ghi.x, nv[4]);
                nv[5] = fmaf(wc, ghi.y, nv[5]);
                nv[6] = fmaf(wc, ghi.z, nv[6]);
                nv[7] = fmaf(wc, ghi.w, nv[7]);
            }
            // Barrel-rotate nv left by rho into w[i] (predicated selects).
            const bool r1 = (rho & 1) != 0, r2 = (rho & 2) != 0, r4 = (rho & 4) != 0;
            float a[8], b[8];
#pragma unroll
            for (int j = 0; j < 8; j++) a[j] = r1 ? nv[(j + 1) & 7] : nv[j];
#pragma unroll
            for (int j = 0; j < 8; j++) b[j] = r2 ? a[(j + 2) & 7] : a[j];
#pragma unroll
            for (int j = 0; j < 8; j++) w[i][j] = r4 ? b[(j + 4) & 7] : b[j];
        }

        if (k < 6) {
            asm volatile("cp.async.wait_group 0;\n" ::: "memory");
            __syncthreads();
        }
    }

    // Final: dot with G7 slice and store.
#pragma unroll
    for (int i = 0; i < EPT; i++) {
        const char* p7 = (const char*)(g7s) + g7off[i] * 32;
        float acc = 0.f;
#pragma unroll
        for (int c = 0; c < 8; c++)
            acc = fmaf(w[i][c], *(const float*)(p7 + (roff[c] >> 2)), acc);
        if (actmask & (1u << i)) out[base + i * THREADS] = acc;
    }
}

extern "C" void kernel_launch(void* const* d_in, const int* in_sizes, int n_in,
                              void* d_out, int out_size)
{
    const float* G0 = (const float*)d_in[0];
    const float* G1 = (const float*)d_in[1];
    const float* G2 = (const float*)d_in[2];
    const float* G3 = (const float*)d_in[3];
    const float* G4 = (const float*)d_in[4];
    const float* G5 = (const float*)d_in[5];
    const float* G6 = (const float*)d_in[6];
    const float* G7 = (const float*)d_in[7];
    const int* states  = (const int*)d_in[8];
    const int* actions = (const int*)d_in[9];
    const int B = in_sizes[9];   // actions element count

    cudaFuncSetAttribute(tt_gather_kernel,
                         cudaFuncAttributeMaxDynamicSharedMemorySize, SMEM_BYTES);

    const int per_block = THREADS * EPT;
    const int grid = (B + per_block - 1) / per_block;
    tt_gather_kernel<<<grid, THREADS, SMEM_BYTES>>>(
        G0, G1, G2, G3, G4, G5, G6, G7, states, actions, (float*)d_out, B);
}

// round 3
// speedup vs baseline: 1.3793x; 1.3793x over previous
#include <cuda_runtime.h>
#include <cstdint>

#define THREADS 448     // 14 warps
#define EPT 4           // elements per thread -> 1792 per block
#define NMODE 256
#define RCORE 8

// Shared memory (floats):
//   buf[0..2] : 3 x 16384 (3 x 64KB) triple-buffered middle-core slabs
//   g0s       : 2048 (8KB)  G0 [idx][r]
//   g7s       : 2048 (8KB)  G7 transposed [idx][r]
#define SMEM_BYTES 212992

// Stage one middle core (8 x 256 x 8 floats = 4096 float4 chunks).
// Global float4 index g = r*512 + u   (u = idx*2 + half)
// Shared float4 index s = idx*16 + half*8 + r  (slice contiguous, chunk bank-group = r)
// Lane mapping: r = lane>>2 (8 groups x 4 lanes -> conflict-free STS),
// 4 consecutive lanes read 64B-contiguous global.
__device__ __forceinline__ void stage_mid(float* dst, const float* __restrict__ src, int tid)
{
    const int lane = tid & 31;
    const int wrp  = tid >> 5;          // 0..13
    const int r    = lane >> 2;
    const int m    = lane & 3;
    const char* gbase = (const char*)src;
    unsigned sbase = (unsigned)__cvta_generic_to_shared(dst);
    const int ub = wrp * 4 + m;         // 0..55
#pragma unroll
    for (int t = 0; t < 10; t++) {
        int u = ub + t * 56;
        if (u < 512) {
            long goff = ((long)(r * 512 + u)) << 4;
            unsigned soff = (unsigned)((((u >> 1) << 4) + ((u & 1) << 3) + r) << 4);
            asm volatile("cp.async.cg.shared.global [%0], [%1], 16;\n"
                         :: "r"(sbase + soff), "l"(gbase + goff) : "memory");
        }
    }
    asm volatile("cp.async.commit_group;\n" ::: "memory");
}

__global__ void __launch_bounds__(THREADS, 1)
tt_gather_kernel(const float* __restrict__ G0, const float* __restrict__ G1,
                 const float* __restrict__ G2, const float* __restrict__ G3,
                 const float* __restrict__ G4, const float* __restrict__ G5,
                 const float* __restrict__ G6, const float* __restrict__ G7,
                 const int* __restrict__ states, const int* __restrict__ actions,
                 float* __restrict__ out, int Btot)
{
    extern __shared__ float smem[];
    float* bufs[3] = { smem, smem + 16384, smem + 32768 };
    float* g0s = smem + 49152;
    float* g7s = smem + 51200;

    const int tid = threadIdx.x;
    const int rho = tid & 7;

    // Prologue: stage G1, G2, G3 into the 3 buffers (3 commit groups, depth-2 pipeline).
    stage_mid(bufs[0], G1, tid);
    stage_mid(bufs[1], G2, tid);
    stage_mid(bufs[2], G3, tid);

    // Stage G0 (512 float4, already [idx][r]).
#pragma unroll
    for (int i = tid; i < 512; i += THREADS)
        ((float4*)g0s)[i] = ((const float4*)G0)[i];

    // Stage G7 transposed: global [r][idx] -> smem [idx][r].
#pragma unroll
    for (int i = tid; i < 2048; i += THREADS) {
        int idx = i & 255, r = i >> 8;
        g7s[idx * 8 + r] = G7[r * 256 + idx];
    }

    // Per-thread rotated chunk byte offsets.
    int roff[8];
#pragma unroll
    for (int c = 0; c < 8; c++) roff[c] = ((c + rho) & 7) << 4;

    // Load indices for my EPT elements.
    const int base = blockIdx.x * (THREADS * EPT) + tid;
    unsigned actmask = 0;
    int g0off[EPT], g7off[EPT], soff[EPT][6];
#pragma unroll
    for (int i = 0; i < EPT; i++) {
        int e = base + i * THREADS;
        bool act = (e < Btot);
        int ec = act ? e : 0;
        if (act) actmask |= (1u << i);
        const int* sp = states + ec * 7;
        g0off[i] = __ldg(sp);
#pragma unroll
        for (int k = 0; k < 6; k++) soff[i][k] = __ldg(sp + k + 1) << 8;  // idx*256 bytes
        g7off[i] = __ldg(actions + ec);
    }

    __syncthreads();   // g0s/g7s visible

    // Init rotated vec from G0: w[j] = vec0[(j+rho)&7]
    float w[EPT][8];
#pragma unroll
    for (int i = 0; i < EPT; i++) {
        const char* p0 = (const char*)(g0s) + g0off[i] * 32;
#pragma unroll
        for (int j = 0; j < 8; j++) w[i][j] = *(const float*)(p0 + (roff[j] >> 2));
    }

    const float* nextG[3] = { G4, G5, G6 };

#pragma unroll
    for (int k = 1; k <= 6; k++) {
        // Wait until buffer for stage k has arrived; allow 2 younger groups in flight.
        if (k <= 4) asm volatile("cp.async.wait_group 2;\n" ::: "memory");
        else if (k == 5) asm volatile("cp.async.wait_group 1;\n" ::: "memory");
        else asm volatile("cp.async.wait_group 0;\n" ::: "memory");
        __syncthreads();

        const float* cur = bufs[(k - 1) % 3];

#pragma unroll
        for (int i = 0; i < EPT; i++) {
            const char* p = (const char*)cur + soff[i][k - 1];
            // Batch all 16 chunk loads first (MLP), then FMA.
            float4 m[16];
#pragma unroll
            for (int c = 0; c < 8; c++) {
                m[c]     = *(const float4*)(p + roff[c]);
                m[c + 8] = *(const float4*)(p + 128 + roff[c]);
            }
            float nv[8];
#pragma unroll
            for (int s = 0; s < 8; s++) nv[s] = 0.f;
#pragma unroll
            for (int c = 0; c < 8; c++) {
                const float wc = w[i][c];
                nv[0] = fmaf(wc, m[c].x, nv[0]);
                nv[1] = fmaf(wc, m[c].y, nv[1]);
                nv[2] = fmaf(wc, m[c].z, nv[2]);
                nv[3] = fmaf(wc, m[c].w, nv[3]);
                nv[4] = fmaf(wc, m[c + 8].x, nv[4]);
                nv[5] = fmaf(wc, m[c + 8].y, nv[5]);
                nv[6] = fmaf(wc, m[c + 8].z, nv[6]);
                nv[7] = fmaf(wc, m[c + 8].w, nv[7]);
            }
            // Barrel-rotate nv left by rho into w[i] (predicated selects).
            const bool r1 = (rho & 1) != 0, r2 = (rho & 2) != 0, r4 = (rho & 4) != 0;
            float a[8], b[8];
#pragma unroll
            for (int j = 0; j < 8; j++) a[j] = r1 ? nv[(j + 1) & 7] : nv[j];
#pragma unroll
            for (int j = 0; j < 8; j++) b[j] = r2 ? a[(j + 2) & 7] : a[j];
#pragma unroll
            for (int j = 0; j < 8; j++) w[i][j] = r4 ? b[(j + 4) & 7] : b[j];
        }

        // Refill this buffer with core k+3 (only after all warps finished reading it).
        if (k <= 3) {
            __syncthreads();
            stage_mid((float*)cur, nextG[k - 1], tid);
        }
    }

    // Final: dot with G7 slice and store.
#pragma unroll
    for (int i = 0; i < EPT; i++) {
        const char* p7 = (const char*)(g7s) + g7off[i] * 32;
        float acc = 0.f;
#pragma unroll
        for (int c = 0; c < 8; c++)
            acc = fmaf(w[i][c], *(const float*)(p7 + (roff[c] >> 2)), acc);
        if (actmask & (1u << i)) out[base + i * THREADS] = acc;
    }
}

extern "C" void kernel_launch(void* const* d_in, const int* in_sizes, int n_in,
                              void* d_out, int out_size)
{
    const float* G0 = (const float*)d_in[0];
    const float* G1 = (const float*)d_in[1];
    const float* G2 = (const float*)d_in[2];
    const float* G3 = (const float*)d_in[3];
    const float* G4 = (const float*)d_in[4];
    const float* G5 = (const float*)d_in[5];
    const float* G6 = (const float*)d_in[6];
    const float* G7 = (const float*)d_in[7];
    const int* states  = (const int*)d_in[8];
    const int* actions = (const int*)d_in[9];
    const int B = in_sizes[9];

    cudaFuncSetAttribute(tt_gather_kernel,
                         cudaFuncAttributeMaxDynamicSharedMemorySize, SMEM_BYTES);

    const int per_block = THREADS * EPT;
    const int grid = (B + per_block - 1) / per_block;
    tt_gather_kernel<<<grid, THREADS, SMEM_BYTES>>>(
        G0, G1, G2, G3, G4, G5, G6, G7, states, actions, (float*)d_out, B);
}